// round 2
// baseline (speedup 1.0000x reference)
#include <cuda_runtime.h>
#include <cstdint>
#include <math.h>

#define DIM   8192
#define BATCH 8
#define TOPK  60

typedef unsigned long long ull;
typedef unsigned int uint;

// ---------------- device scratch (no allocations allowed) ----------------
__device__ float g_act[BATCH * DIM];                 // step-1 sigmoid output
__device__ float g_z2 [BATCH * DIM];                 // step-2 sigmoid output
__device__ ull   g_sdr_paired[(BATCH / 2) * DIM];    // sdr packed as (b,b+1) f32 pairs
__device__ float g_vals[BATCH * 64];                 // top-k values (step 1)
__device__ int   g_idxs[BATCH * 64];                 // top-k indices (step 1)

// ---------------- helpers ----------------
__device__ __forceinline__ float sigmoidf(float x) {
    return 1.0f / (1.0f + expf(-x));
}
__device__ __forceinline__ ull pack2(float x, float y) {
    ull r; asm("mov.b64 %0, {%1,%2};" : "=l"(r) : "f"(x), "f"(y)); return r;
}
__device__ __forceinline__ void unpack2(ull v, float &x, float &y) {
    asm("mov.b64 {%0,%1}, %2;" : "=f"(x), "=f"(y) : "l"(v));
}
// packed f32x2 FMA (sm_100+): d = a*b + d  (elementwise on two fp32 lanes)
__device__ __forceinline__ void fma2(ull &d, ull a, ull b) {
    asm("fma.rn.f32x2 %0, %1, %2, %0;" : "+l"(d) : "l"(a), "l"(b));
}

// ---------------- kernel 0: pack sdr into batch-pairs ----------------
__global__ void pair_sdr_kernel(const float* __restrict__ sdr) {
    int k = blockIdx.x * blockDim.x + threadIdx.x;
    if (k < DIM) {
#pragma unroll
        for (int p = 0; p < BATCH / 2; p++) {
            g_sdr_paired[p * DIM + k] =
                pack2(sdr[(2 * p) * DIM + k], sdr[(2 * p + 1) * DIM + k]);
        }
    }
}

// ---------------- kernel 1: dense GEMV-8 + sigmoid ----------------
// out[b][j] = sigmoid( sum_k sdr[b][k] * syn[j][k] )
// warp handles 4 consecutive j rows; lanes stride over k; f32x2 FMA over batch pairs.
__global__ __launch_bounds__(256) void gemv_dense_kernel(const float* __restrict__ syn) {
    int warp = blockIdx.x * 8 + (threadIdx.x >> 5);   // 2048 warps total
    int lane = threadIdx.x & 31;
    int j0 = warp * 4;

    const float* r0 = syn + (size_t)(j0 + 0) * DIM;
    const float* r1 = syn + (size_t)(j0 + 1) * DIM;
    const float* r2 = syn + (size_t)(j0 + 2) * DIM;
    const float* r3 = syn + (size_t)(j0 + 3) * DIM;

    ull acc[4][4];
#pragma unroll
    for (int jj = 0; jj < 4; jj++)
#pragma unroll
        for (int p = 0; p < 4; p++) acc[jj][p] = 0ull;  // (0.0f, 0.0f)

#pragma unroll 2
    for (int k = lane; k < DIM; k += 32) {
        ull s0 = g_sdr_paired[0 * DIM + k];
        ull s1 = g_sdr_paired[1 * DIM + k];
        ull s2 = g_sdr_paired[2 * DIM + k];
        ull s3 = g_sdr_paired[3 * DIM + k];

        float a0 = r0[k], a1 = r1[k], a2 = r2[k], a3 = r3[k];
        ull p0 = pack2(a0, a0), p1 = pack2(a1, a1);
        ull p2 = pack2(a2, a2), p3 = pack2(a3, a3);

        fma2(acc[0][0], p0, s0); fma2(acc[0][1], p0, s1);
        fma2(acc[0][2], p0, s2); fma2(acc[0][3], p0, s3);
        fma2(acc[1][0], p1, s0); fma2(acc[1][1], p1, s1);
        fma2(acc[1][2], p1, s2); fma2(acc[1][3], p1, s3);
        fma2(acc[2][0], p2, s0); fma2(acc[2][1], p2, s1);
        fma2(acc[2][2], p2, s2); fma2(acc[2][3], p2, s3);
        fma2(acc[3][0], p3, s0); fma2(acc[3][1], p3, s1);
        fma2(acc[3][2], p3, s2); fma2(acc[3][3], p3, s3);
    }

    // warp reduction + write
#pragma unroll
    for (int jj = 0; jj < 4; jj++) {
#pragma unroll
        for (int p = 0; p < 4; p++) {
            float x, y;
            unpack2(acc[jj][p], x, y);
#pragma unroll
            for (int o = 16; o > 0; o >>= 1) {
                x += __shfl_down_sync(0xFFFFFFFFu, x, o);
                y += __shfl_down_sync(0xFFFFFFFFu, y, o);
            }
            if (lane == 0) {
                g_act[(size_t)(2 * p)     * DIM + (j0 + jj)] = sigmoidf(x);
                g_act[(size_t)(2 * p + 1) * DIM + (j0 + jj)] = sigmoidf(y);
            }
        }
    }
}

// ---------------- kernel 2/4: per-row top-k ----------------
// phase 0: read g_act, write compact (val, idx) lists.
// phase 1: read g_z2, write final dense output row (zeros + selected values).
// Exact jax.lax.top_k semantics: k largest; ties at the cutoff resolved by
// lowest index (index-ordered prefix scan over ties).
__global__ __launch_bounds__(256) void topk_kernel(float* __restrict__ full_out, int phase) {
    int b   = blockIdx.x;
    int tid = threadIdx.x;
    const float* row = (phase == 0 ? g_act : g_z2) + (size_t)b * DIM;

    // each thread owns 32 contiguous elements (index-ordered for tie handling)
    uint ub[32];
    int base = tid * 32;
#pragma unroll
    for (int i = 0; i < 32; i++) ub[i] = __float_as_uint(row[base + i]);

    __shared__ int s_cv[40];     // [0..30] search counts, [32] cnt_gt, [33] slot ctr
    __shared__ int s_scan[256];
    if (tid < 40) s_cv[tid] = 0;

    if (phase == 1) {            // zero output row (overlaps with search)
        float* orow = full_out + (size_t)b * DIM;
        for (int i = tid; i < DIM; i += 256) orow[i] = 0.0f;
    }
    __syncthreads();

    // binary search over float bit patterns (all values in [0,1] -> monotone bits)
    uint lo = 0u, hi = 0x3F800001u;  // just above 1.0f
    int it = 0;
    while (hi - lo > 1u) {
        uint mid = lo + ((hi - lo) >> 1);
        int c = 0;
#pragma unroll
        for (int i = 0; i < 32; i++) c += (ub[i] >= mid);
#pragma unroll
        for (int o = 16; o > 0; o >>= 1) c += __shfl_xor_sync(0xFFFFFFFFu, c, o);
        if ((tid & 31) == 0) atomicAdd(&s_cv[it], c);
        __syncthreads();
        int tot = s_cv[it];
        it++;
        if (tot >= TOPK) lo = mid; else hi = mid;
    }
    uint T = lo;  // bits of the k-th largest value

    // count strictly-greater elements
    {
        int c = 0;
#pragma unroll
        for (int i = 0; i < 32; i++) c += (ub[i] > T);
#pragma unroll
        for (int o = 16; o > 0; o >>= 1) c += __shfl_xor_sync(0xFFFFFFFFu, c, o);
        if ((tid & 31) == 0) atomicAdd(&s_cv[32], c);
    }
    __syncthreads();
    int cnt_gt = s_cv[32];
    int needed = TOPK - cnt_gt;  // ties (== T) to take, lowest index first

    // index-ordered prefix scan of tie counts
    int tie_local = 0;
#pragma unroll
    for (int i = 0; i < 32; i++) tie_local += (ub[i] == T);
    s_scan[tid] = tie_local;
    __syncthreads();
    for (int off = 1; off < 256; off <<= 1) {
        int add = (tid >= off) ? s_scan[tid - off] : 0;
        __syncthreads();
        s_scan[tid] += add;
        __syncthreads();
    }
    int excl = s_scan[tid] - tie_local;

    // selection
    float* orow = full_out + (size_t)b * DIM;
    int tw = 0;
#pragma unroll
    for (int i = 0; i < 32; i++) {
        uint u = ub[i];
        if (u > T) {
            if (phase == 0) {
                int slot = atomicAdd(&s_cv[33], 1);
                g_vals[b * 64 + slot] = __uint_as_float(u);
                g_idxs[b * 64 + slot] = base + i;
            } else {
                orow[base + i] = __uint_as_float(u);
            }
        } else if (u == T) {
            int rank = excl + tw;
            tw++;
            if (rank < needed) {
                if (phase == 0) {
                    int slot = cnt_gt + rank;
                    g_vals[b * 64 + slot] = __uint_as_float(u);
                    g_idxs[b * 64 + slot] = base + i;
                } else {
                    orow[base + i] = __uint_as_float(u);
                }
            }
        }
    }
}

// ---------------- kernel 3: sparse GEMV (60 nnz per row) + sigmoid ----------------
// z2[b][j] = sigmoid( sum_t val[b][t] * syn[j][idx[b][t]] )
__global__ __launch_bounds__(256) void gemv_sparse_kernel(const float* __restrict__ syn) {
    int b = blockIdx.y;
    int j = blockIdx.x * 256 + threadIdx.x;

    __shared__ float sv[TOPK];
    __shared__ int   si[TOPK];
    if (threadIdx.x < TOPK) {
        sv[threadIdx.x] = g_vals[b * 64 + threadIdx.x];
        si[threadIdx.x] = g_idxs[b * 64 + threadIdx.x];
    }
    __syncthreads();

    const float* row = syn + (size_t)j * DIM;
    float acc = 0.0f;
#pragma unroll 10
    for (int t = 0; t < TOPK; t++) {
        acc += sv[t] * __ldg(&row[si[t]]);
    }
    g_z2[(size_t)b * DIM + j] = sigmoidf(acc);
}

// ---------------- launch ----------------
extern "C" void kernel_launch(void* const* d_in, const int* in_sizes, int n_in,
                              void* d_out, int out_size) {
    const float* sdr = (const float*)d_in[0];   // [8, 8192]
    const float* syn = (const float*)d_in[1];   // [8192, 8192]
    float* out = (float*)d_out;                 // [8, 8192]
    (void)in_sizes; (void)n_in; (void)out_size;

    pair_sdr_kernel<<<DIM / 256, 256>>>(sdr);
    gemv_dense_kernel<<<DIM / 32, 256>>>(syn);       // 256 blocks x 8 warps x 4 rows
    topk_kernel<<<BATCH, 256>>>(out, /*phase=*/0);   // -> compact (val, idx)
    {
        dim3 grid(DIM / 256, BATCH);
        gemv_sparse_kernel<<<grid, 256>>>(syn);
    }
    topk_kernel<<<BATCH, 256>>>(out, /*phase=*/1);   // -> dense output rows
}

// round 3
// speedup vs baseline: 1.4743x; 1.4743x over previous
#include <cuda_runtime.h>
#include <cstdint>
#include <math.h>

#define DIM   8192
#define BATCH 8
#define TOPK  60

typedef unsigned long long ull;
typedef unsigned int uint;

// ---------------- device scratch (no allocations allowed) ----------------
__device__ float g_act[BATCH * DIM];               // step-1 sigmoid output
__device__ float g_z2 [BATCH * DIM];               // step-2 sigmoid output
__device__ ull   g_sdr_paired[(BATCH / 2) * DIM];  // sdr packed as (b,b+1) f32 pairs
__device__ float g_vals[BATCH * 64];               // top-k values (step 1), [b*64+t]
__device__ int   g_idxs[BATCH * 64];               // top-k indices (step 1)

// ---------------- helpers ----------------
__device__ __forceinline__ float sigmoidf(float x) {
    return 1.0f / (1.0f + expf(-x));   // precise expf: keeps top-k selection stable
}
__device__ __forceinline__ ull pack2(float x, float y) {
    ull r; asm("mov.b64 %0, {%1,%2};" : "=l"(r) : "f"(x), "f"(y)); return r;
}
__device__ __forceinline__ void unpack2(ull v, float &x, float &y) {
    asm("mov.b64 {%0,%1}, %2;" : "=f"(x), "=f"(y) : "l"(v));
}
__device__ __forceinline__ void fma2(ull &d, ull a, ull b) {
    asm("fma.rn.f32x2 %0, %1, %2, %0;" : "+l"(d) : "l"(a), "l"(b));
}

// ---------------- kernel 0: pack sdr into batch-pairs ----------------
__global__ void pair_sdr_kernel(const float* __restrict__ sdr) {
    int k = blockIdx.x * blockDim.x + threadIdx.x;
    if (k < DIM) {
#pragma unroll
        for (int p = 0; p < BATCH / 2; p++) {
            g_sdr_paired[p * DIM + k] =
                pack2(sdr[(2 * p) * DIM + k], sdr[(2 * p + 1) * DIM + k]);
        }
    }
}

// ---------------- kernel 1: dense GEMV-8 + sigmoid ----------------
// Warp owns 4 consecutive rows j; lanes stride over k in float4 units.
// Body prefetches 4 stages (16 float4 lines) to keep ~16 DRAM lines in
// flight per warp; sdr pairs come from L1 via 16B loads.
__global__ __launch_bounds__(256, 2) void gemv_dense_kernel(const float* __restrict__ syn) {
    int warp = blockIdx.x * 8 + (threadIdx.x >> 5);   // 2048 warps
    int lane = threadIdx.x & 31;
    int j0 = warp * 4;

    const float4* r0 = (const float4*)(syn + (size_t)(j0 + 0) * DIM);
    const float4* r1 = (const float4*)(syn + (size_t)(j0 + 1) * DIM);
    const float4* r2 = (const float4*)(syn + (size_t)(j0 + 2) * DIM);
    const float4* r3 = (const float4*)(syn + (size_t)(j0 + 3) * DIM);

    ull acc[4][4];
#pragma unroll
    for (int i = 0; i < 4; i++)
#pragma unroll
        for (int p = 0; p < 4; p++) acc[i][p] = 0ull;

    for (int t = 0; t < DIM / 4; t += 128) {          // 16 bodies
        float4 a0[4], a1[4], a2[4], a3[4];
#pragma unroll
        for (int u = 0; u < 4; u++) {
            int k4 = t + u * 32 + lane;
            a0[u] = r0[k4]; a1[u] = r1[k4]; a2[u] = r2[k4]; a3[u] = r3[k4];
        }
#pragma unroll
        for (int u = 0; u < 4; u++) {
            int k = (t + u * 32 + lane) * 4;
            ulonglong2 sA[4], sB[4];                  // sA[p]=(k,k+1), sB[p]=(k+2,k+3)
#pragma unroll
            for (int p = 0; p < 4; p++) {
                const ulonglong2* sp = (const ulonglong2*)&g_sdr_paired[p * DIM + k];
                sA[p] = sp[0];
                sB[p] = sp[1];
            }
#pragma unroll
            for (int i = 0; i < 4; i++) {
                float4 a = (i == 0 ? a0[u] : i == 1 ? a1[u] : i == 2 ? a2[u] : a3[u]);
                ull px = pack2(a.x, a.x), py = pack2(a.y, a.y);
                ull pz = pack2(a.z, a.z), pw = pack2(a.w, a.w);
#pragma unroll
                for (int p = 0; p < 4; p++) {
                    fma2(acc[i][p], px, sA[p].x);
                    fma2(acc[i][p], py, sA[p].y);
                    fma2(acc[i][p], pz, sB[p].x);
                    fma2(acc[i][p], pw, sB[p].y);
                }
            }
        }
    }

#pragma unroll
    for (int i = 0; i < 4; i++) {
#pragma unroll
        for (int p = 0; p < 4; p++) {
            float x, y;
            unpack2(acc[i][p], x, y);
#pragma unroll
            for (int o = 16; o > 0; o >>= 1) {
                x += __shfl_down_sync(0xFFFFFFFFu, x, o);
                y += __shfl_down_sync(0xFFFFFFFFu, y, o);
            }
            if (lane == 0) {
                g_act[(size_t)(2 * p)     * DIM + (j0 + i)] = sigmoidf(x);
                g_act[(size_t)(2 * p + 1) * DIM + (j0 + i)] = sigmoidf(y);
            }
        }
    }
}

// ---------------- kernel 2/4: per-row top-k (512 threads, coalesced) ----------------
// phase 0: read g_act -> compact (val, idx) lists (order arbitrary).
// phase 1: read g_z2  -> final dense output row (zeros + selected values).
// Exact jax.lax.top_k tie semantics via a tiny sorted tie-position list.
__global__ __launch_bounds__(512) void topk_kernel(float* __restrict__ full_out, int phase) {
    int b   = blockIdx.x;
    int tid = threadIdx.x;
    const float* row = (phase == 0 ? g_act : g_z2) + (size_t)b * DIM;
    const float4* row4 = (const float4*)row;

    // coalesced ownership: thread owns float4s at (i*512 + tid), i = 0..3
    uint ub[16];
#pragma unroll
    for (int i = 0; i < 4; i++) {
        float4 v = row4[i * 512 + tid];
        ub[i * 4 + 0] = __float_as_uint(v.x);
        ub[i * 4 + 1] = __float_as_uint(v.y);
        ub[i * 4 + 2] = __float_as_uint(v.z);
        ub[i * 4 + 3] = __float_as_uint(v.w);
    }

    __shared__ int s_cnt[36];      // [0..31] search iters, [33] cnt_gt
    __shared__ int s_tie[64];
    __shared__ int s_ntie, s_slot;
    if (tid < 36) s_cnt[tid] = 0;
    if (tid == 0) { s_ntie = 0; s_slot = 0; }

    if (phase == 1) {              // zero output row, overlapped with search
        float4* o4 = (float4*)(full_out + (size_t)b * DIM);
        float4 z = make_float4(0.f, 0.f, 0.f, 0.f);
#pragma unroll
        for (int i = 0; i < 4; i++) o4[i * 512 + tid] = z;
    }
    __syncthreads();

    // binary search over float bits (sigmoid output in (0,1) -> bits monotone)
    uint lo = 0u, hi = 0x3F800001u;
    int it = 0;
    while (hi - lo > 1u) {
        uint mid = lo + ((hi - lo) >> 1);
        int c = 0;
#pragma unroll
        for (int i = 0; i < 16; i++) c += (ub[i] >= mid);
#pragma unroll
        for (int o = 16; o > 0; o >>= 1) c += __shfl_xor_sync(0xFFFFFFFFu, c, o);
        if ((tid & 31) == 0) atomicAdd(&s_cnt[it], c);
        __syncthreads();
        int tot = s_cnt[it];
        it++;
        if (tot >= TOPK) lo = mid; else hi = mid;
    }
    uint T = lo;   // bits of the k-th largest value

    // count strictly-greater, collect tie positions
    {
        int c = 0;
#pragma unroll
        for (int i = 0; i < 16; i++) c += (ub[i] > T);
#pragma unroll
        for (int o = 16; o > 0; o >>= 1) c += __shfl_xor_sync(0xFFFFFFFFu, c, o);
        if ((tid & 31) == 0) atomicAdd(&s_cnt[33], c);
    }
#pragma unroll
    for (int i = 0; i < 16; i++) {
        if (ub[i] == T) {
            int pos = (i >> 2) * 2048 + tid * 4 + (i & 3);
            int t = atomicAdd(&s_ntie, 1);
            if (t < 64) s_tie[t] = pos;
        }
    }
    __syncthreads();
    int cnt_gt = s_cnt[33];
    int needed = TOPK - cnt_gt;        // ties to take, lowest index first
    int ntie = min(s_ntie, 64);

    if (tid == 0) {                    // tiny insertion sort of tie positions
        for (int x = 1; x < ntie; x++) {
            int v = s_tie[x], y = x - 1;
            while (y >= 0 && s_tie[y] > v) { s_tie[y + 1] = s_tie[y]; y--; }
            s_tie[y + 1] = v;
        }
    }
    __syncthreads();
    int nsel = min(needed, 64);

    float* orow = full_out + (size_t)b * DIM;
#pragma unroll
    for (int i = 0; i < 16; i++) {
        uint u = ub[i];
        int pos = (i >> 2) * 2048 + tid * 4 + (i & 3);
        if (u > T) {
            if (phase == 0) {
                int slot = atomicAdd(&s_slot, 1);
                g_vals[b * 64 + slot] = __uint_as_float(u);
                g_idxs[b * 64 + slot] = pos;
            } else {
                orow[pos] = __uint_as_float(u);
            }
        } else if (u == T) {
            bool sel = false;
            for (int q = 0; q < nsel; q++) sel |= (s_tie[q] == pos);
            if (sel) {
                if (phase == 0) {
                    int slot = atomicAdd(&s_slot, 1);
                    g_vals[b * 64 + slot] = __uint_as_float(u);
                    g_idxs[b * 64 + slot] = pos;
                } else {
                    orow[pos] = __uint_as_float(u);
                }
            }
        }
    }
}

// ---------------- kernel 3: sparse GEMV, all batches per thread ----------------
// z2[b][j] = sigmoid( sum_t val[b][t] * syn[j][idx[b][t]] )
// One pass over j: each 32B sector fetched once per thread; cross-batch
// duplicate indices hit L1.
__global__ __launch_bounds__(64) void gemv_sparse_kernel(const float* __restrict__ syn) {
    int j = blockIdx.x * 64 + threadIdx.x;

    __shared__ float sv[BATCH * 64];
    __shared__ int   si[BATCH * 64];
    for (int t = threadIdx.x; t < BATCH * 64; t += 64) {
        sv[t] = g_vals[t];
        si[t] = g_idxs[t];
    }
    __syncthreads();

    const float* __restrict__ row = syn + (size_t)j * DIM;
    float acc[BATCH];
#pragma unroll
    for (int b = 0; b < BATCH; b++) acc[b] = 0.0f;

#pragma unroll
    for (int b = 0; b < BATCH; b++) {
#pragma unroll 12
        for (int t = 0; t < TOPK; t++) {
            acc[b] += sv[b * 64 + t] * __ldg(&row[si[b * 64 + t]]);
        }
    }

#pragma unroll
    for (int b = 0; b < BATCH; b++) {
        g_z2[(size_t)b * DIM + j] = sigmoidf(acc[b]);
    }
}

// ---------------- launch ----------------
extern "C" void kernel_launch(void* const* d_in, const int* in_sizes, int n_in,
                              void* d_out, int out_size) {
    const float* sdr = (const float*)d_in[0];   // [8, 8192]
    const float* syn = (const float*)d_in[1];   // [8192, 8192]
    float* out = (float*)d_out;                 // [8, 8192]
    (void)in_sizes; (void)n_in; (void)out_size;

    pair_sdr_kernel<<<DIM / 256, 256>>>(sdr);
    gemv_dense_kernel<<<DIM / 32, 256>>>(syn);       // 256 blocks, 4 rows/warp
    topk_kernel<<<BATCH, 512>>>(out, /*phase=*/0);   // -> compact (val, idx)
    gemv_sparse_kernel<<<DIM / 64, 64>>>(syn);       // 128 blocks, all batches/thread
    topk_kernel<<<BATCH, 512>>>(out, /*phase=*/1);   // -> dense output rows
}

// round 4
// speedup vs baseline: 1.8670x; 1.2663x over previous
#include <cuda_runtime.h>
#include <cstdint>
#include <math.h>

#define DIM   8192
#define BATCH 8
#define TOPK  60

typedef unsigned long long ull;
typedef unsigned int uint;

// ---------------- device scratch (no allocations allowed) ----------------
__device__ float g_act[BATCH * DIM];               // step-1 sigmoid output
__device__ float g_z2 [BATCH * DIM];               // step-2 sigmoid output
__device__ ull   g_sdr_paired[(BATCH / 2) * DIM];  // sdr packed as (b,b+1) f32 pairs
__device__ float g_vals[BATCH * 64];               // top-k values, sorted by index
__device__ int   g_idxs[BATCH * 64];               // top-k indices, ascending

// ---------------- helpers ----------------
__device__ __forceinline__ float sigmoidf(float x) {
    return 1.0f / (1.0f + expf(-x));   // precise expf: selection must match reference
}
__device__ __forceinline__ ull pack2(float x, float y) {
    ull r; asm("mov.b64 %0, {%1,%2};" : "=l"(r) : "f"(x), "f"(y)); return r;
}
__device__ __forceinline__ void unpack2(ull v, float &x, float &y) {
    asm("mov.b64 {%0,%1}, %2;" : "=f"(x), "=f"(y) : "l"(v));
}
__device__ __forceinline__ void fma2(ull &d, ull a, ull b) {
    asm("fma.rn.f32x2 %0, %1, %2, %0;" : "+l"(d) : "l"(a), "l"(b));
}

// ---------------- kernel 0: pack sdr into batch-pairs ----------------
__global__ void pair_sdr_kernel(const float* __restrict__ sdr) {
    int k = blockIdx.x * blockDim.x + threadIdx.x;
    if (k < DIM) {
#pragma unroll
        for (int p = 0; p < BATCH / 2; p++) {
            g_sdr_paired[p * DIM + k] =
                pack2(sdr[(2 * p) * DIM + k], sdr[(2 * p + 1) * DIM + k]);
        }
    }
}

// ---------------- kernel 1: dense GEMV-8 + sigmoid ----------------
// Warp owns 4 consecutive rows j; lanes stride over k in float4 units;
// 16 float4 lines in flight per warp body.
__global__ __launch_bounds__(256, 2) void gemv_dense_kernel(const float* __restrict__ syn) {
    int warp = blockIdx.x * 8 + (threadIdx.x >> 5);   // 2048 warps
    int lane = threadIdx.x & 31;
    int j0 = warp * 4;

    const float4* r0 = (const float4*)(syn + (size_t)(j0 + 0) * DIM);
    const float4* r1 = (const float4*)(syn + (size_t)(j0 + 1) * DIM);
    const float4* r2 = (const float4*)(syn + (size_t)(j0 + 2) * DIM);
    const float4* r3 = (const float4*)(syn + (size_t)(j0 + 3) * DIM);

    ull acc[4][4];
#pragma unroll
    for (int i = 0; i < 4; i++)
#pragma unroll
        for (int p = 0; p < 4; p++) acc[i][p] = 0ull;

    for (int t = 0; t < DIM / 4; t += 128) {          // 16 bodies
        float4 a0[4], a1[4], a2[4], a3[4];
#pragma unroll
        for (int u = 0; u < 4; u++) {
            int k4 = t + u * 32 + lane;
            a0[u] = r0[k4]; a1[u] = r1[k4]; a2[u] = r2[k4]; a3[u] = r3[k4];
        }
#pragma unroll
        for (int u = 0; u < 4; u++) {
            int k = (t + u * 32 + lane) * 4;
            ulonglong2 sA[4], sB[4];
#pragma unroll
            for (int p = 0; p < 4; p++) {
                const ulonglong2* sp = (const ulonglong2*)&g_sdr_paired[p * DIM + k];
                sA[p] = sp[0];
                sB[p] = sp[1];
            }
#pragma unroll
            for (int i = 0; i < 4; i++) {
                float4 a = (i == 0 ? a0[u] : i == 1 ? a1[u] : i == 2 ? a2[u] : a3[u]);
                ull px = pack2(a.x, a.x), py = pack2(a.y, a.y);
                ull pz = pack2(a.z, a.z), pw = pack2(a.w, a.w);
#pragma unroll
                for (int p = 0; p < 4; p++) {
                    fma2(acc[i][p], px, sA[p].x);
                    fma2(acc[i][p], py, sA[p].y);
                    fma2(acc[i][p], pz, sB[p].x);
                    fma2(acc[i][p], pw, sB[p].y);
                }
            }
        }
    }

#pragma unroll
    for (int i = 0; i < 4; i++) {
#pragma unroll
        for (int p = 0; p < 4; p++) {
            float x, y;
            unpack2(acc[i][p], x, y);
#pragma unroll
            for (int o = 16; o > 0; o >>= 1) {
                x += __shfl_down_sync(0xFFFFFFFFu, x, o);
                y += __shfl_down_sync(0xFFFFFFFFu, y, o);
            }
            if (lane == 0) {
                g_act[(size_t)(2 * p)     * DIM + (j0 + i)] = sigmoidf(x);
                g_act[(size_t)(2 * p + 1) * DIM + (j0 + i)] = sigmoidf(y);
            }
        }
    }
}

// ---------------- kernel 2/4: per-row top-k (512 threads, coalesced) ----------------
// phase 0: read g_act -> compact (val, idx) list, SORTED by index ascending.
// phase 1: read g_z2  -> final dense output row (zeros + selected values).
// Exact jax.lax.top_k tie semantics (lowest index wins at the cutoff).
__global__ __launch_bounds__(512) void topk_kernel(float* __restrict__ full_out, int phase) {
    int b   = blockIdx.x;
    int tid = threadIdx.x;
    const float* row = (phase == 0 ? g_act : g_z2) + (size_t)b * DIM;
    const float4* row4 = (const float4*)row;

    uint ub[16];
#pragma unroll
    for (int i = 0; i < 4; i++) {
        float4 v = row4[i * 512 + tid];
        ub[i * 4 + 0] = __float_as_uint(v.x);
        ub[i * 4 + 1] = __float_as_uint(v.y);
        ub[i * 4 + 2] = __float_as_uint(v.z);
        ub[i * 4 + 3] = __float_as_uint(v.w);
    }

    __shared__ int   s_cnt[36];      // [0..31] search iters, [33] cnt_gt
    __shared__ int   s_tie[64];
    __shared__ float s_outv[64];
    __shared__ int   s_outi[64];
    __shared__ int   s_ntie, s_slot;
    if (tid < 36) s_cnt[tid] = 0;
    if (tid == 0) { s_ntie = 0; s_slot = 0; }

    if (phase == 1) {                // zero output row, overlapped with search
        float4* o4 = (float4*)(full_out + (size_t)b * DIM);
        float4 z = make_float4(0.f, 0.f, 0.f, 0.f);
#pragma unroll
        for (int i = 0; i < 4; i++) o4[i * 512 + tid] = z;
    }
    __syncthreads();

    // binary search over float bits (sigmoid output in (0,1) -> bits monotone)
    uint lo = 0u, hi = 0x3F800001u;
    int it = 0;
    while (hi - lo > 1u) {
        uint mid = lo + ((hi - lo) >> 1);
        int c = 0;
#pragma unroll
        for (int i = 0; i < 16; i++) c += (ub[i] >= mid);
#pragma unroll
        for (int o = 16; o > 0; o >>= 1) c += __shfl_xor_sync(0xFFFFFFFFu, c, o);
        if ((tid & 31) == 0) atomicAdd(&s_cnt[it], c);
        __syncthreads();
        int tot = s_cnt[it];
        it++;
        if (tot >= TOPK) lo = mid; else hi = mid;
    }
    uint T = lo;   // bits of the k-th largest value

    {
        int c = 0;
#pragma unroll
        for (int i = 0; i < 16; i++) c += (ub[i] > T);
#pragma unroll
        for (int o = 16; o > 0; o >>= 1) c += __shfl_xor_sync(0xFFFFFFFFu, c, o);
        if ((tid & 31) == 0) atomicAdd(&s_cnt[33], c);
    }
#pragma unroll
    for (int i = 0; i < 16; i++) {
        if (ub[i] == T) {
            int pos = (i >> 2) * 2048 + tid * 4 + (i & 3);
            int t = atomicAdd(&s_ntie, 1);
            if (t < 64) s_tie[t] = pos;
        }
    }
    __syncthreads();
    int cnt_gt = s_cnt[33];
    int needed = TOPK - cnt_gt;        // ties to take, lowest index first
    int ntie = min(s_ntie, 64);

    if (tid == 0) {                    // tiny insertion sort of tie positions
        for (int x = 1; x < ntie; x++) {
            int v = s_tie[x], y = x - 1;
            while (y >= 0 && s_tie[y] > v) { s_tie[y + 1] = s_tie[y]; y--; }
            s_tie[y + 1] = v;
        }
    }
    __syncthreads();
    int nsel = min(needed, 64);

    float* orow = full_out + (size_t)b * DIM;
#pragma unroll
    for (int i = 0; i < 16; i++) {
        uint u = ub[i];
        int pos = (i >> 2) * 2048 + tid * 4 + (i & 3);
        bool take = false;
        if (u > T) {
            take = true;
        } else if (u == T) {
            for (int q = 0; q < nsel; q++) take |= (s_tie[q] == pos);
        }
        if (take) {
            if (phase == 0) {
                int slot = atomicAdd(&s_slot, 1);
                s_outv[slot] = __uint_as_float(u);
                s_outi[slot] = pos;
            } else {
                orow[pos] = __uint_as_float(u);
            }
        }
    }

    if (phase == 0) {
        // parallel rank-sort the 60 selected entries by index ascending
        __syncthreads();
        if (tid < TOPK) {
            int my_i = s_outi[tid];
            float my_v = s_outv[tid];
            int rank = 0;
#pragma unroll 10
            for (int q = 0; q < TOPK; q++) rank += (s_outi[q] < my_i);
            g_vals[b * 64 + rank] = my_v;
            g_idxs[b * 64 + rank] = my_i;
        }
    }
}

// ---------------- kernel 3: sparse GEMV + sigmoid ----------------
// z2[b][j] = sigmoid( sum_t val[b][t] * syn[j][idx[b][t]] )
// Block = 16 j x 8 b (128 threads), 512 blocks -> 65536 threads.
// Indices are sorted ascending -> consecutive t's touch nearby columns
// (DRAM row-buffer locality). 60 independent LDGs per thread, fully unrolled.
__global__ __launch_bounds__(128) void gemv_sparse_kernel(const float* __restrict__ syn) {
    int jj = threadIdx.x & 15;          // 0..15
    int b  = threadIdx.x >> 4;          // 0..7
    int j  = blockIdx.x * 16 + jj;

    __shared__ float sv[BATCH * 64];
    __shared__ int   si[BATCH * 64];
    for (int t = threadIdx.x; t < BATCH * 64; t += 128) {
        sv[t] = g_vals[t];
        si[t] = g_idxs[t];
    }
    __syncthreads();

    const float* __restrict__ row = syn + (size_t)j * DIM;
    float acc = 0.0f;
#pragma unroll
    for (int t = 0; t < TOPK; t++) {
        acc += sv[b * 64 + t] * __ldg(&row[si[b * 64 + t]]);
    }
    g_z2[(size_t)b * DIM + j] = sigmoidf(acc);
}

// ---------------- launch ----------------
extern "C" void kernel_launch(void* const* d_in, const int* in_sizes, int n_in,
                              void* d_out, int out_size) {
    const float* sdr = (const float*)d_in[0];   // [8, 8192]
    const float* syn = (const float*)d_in[1];   // [8192, 8192]
    float* out = (float*)d_out;                 // [8, 8192]
    (void)in_sizes; (void)n_in; (void)out_size;

    pair_sdr_kernel<<<DIM / 256, 256>>>(sdr);
    gemv_dense_kernel<<<DIM / 32, 256>>>(syn);       // 256 blocks, 4 rows/warp
    topk_kernel<<<BATCH, 512>>>(out, /*phase=*/0);   // -> sorted (val, idx)
    gemv_sparse_kernel<<<DIM / 16, 128>>>(syn);      // 512 blocks, 16j x 8b
    topk_kernel<<<BATCH, 512>>>(out, /*phase=*/1);   // -> dense output rows
}